// round 12
// baseline (speedup 1.0000x reference)
#include <cuda_runtime.h>
#include <math.h>
#include <float.h>

#define BB 32
#define QQ 900
#define MM 128
#define KC 80
#define KP1 81
#define NT 16                      // q-tiles per image (16 * 64-row halves)
#define INFF __int_as_float(0x7f800000)
#define DEAD64 0xffffffffffffffffull
#define FULL 0xffffffffu

__device__ float g_costT[BB * MM * QQ];                 // [b][m][q] for rescans
__device__ unsigned long long g_top[BB * NT * MM * 4];
__device__ float g_lse[BB * QQ];
__device__ float g_b80[BB * QQ];
__device__ float g_acc[3];
__device__ unsigned g_done;
__device__ unsigned g_ready[BB];

__device__ __forceinline__ unsigned ford(float f) {
    unsigned u = __float_as_uint(f);
    return u ^ ((u >> 31) ? 0xffffffffu : 0x80000000u);
}

#define SMEM_TOTAL 49152

__global__ void __launch_bounds__(256) k_fused(
    const float* __restrict__ logits,
    const float* __restrict__ pboxes,
    const float* __restrict__ tboxes,
    const float* __restrict__ sizes,
    const int*   __restrict__ labels,
    float* __restrict__ out) {
    extern __shared__ char smraw[];
    int bid = blockIdx.x, tid = threadIdx.x;

    if (bid < BB * 8) {
        // ================= COST BLOCK: image b, one 128-row q-tile ============
        int b = bid >> 3, t = bid & 7;
        int q0 = t * 128;
        int nrow = min(128, QQ - q0);
        float* sprob = (float*)smraw;                 // 128*81
        float* tn0 = sprob + 128 * KP1;
        float* tn1 = tn0 + MM; float* tn2 = tn1 + MM; float* tn3 = tn2 + MM;
        float* tc  = tn3 + MM; float* ts  = tc  + MM;
        int*   tl  = (int*)(ts + MM);
        float* pq0 = (float*)(tl + MM);
        float* pq1 = pq0 + 128; float* pq2 = pq1 + 128; float* pq3 = pq2 + 128;
        float* pqc = pq3 + 128; float* pqs = pqc + 128;

        float H = sizes[b * 2 + 0], W = sizes[b * 2 + 1];
        if (tid < MM) {
            const float* tb = tboxes + ((size_t)b * MM + tid) * 5;
            tn0[tid] = tb[0] / W; tn1[tid] = tb[1] / H;
            tn2[tid] = tb[2] / W; tn3[tid] = tb[3] / H;
            float sn, cs; sincosf(tb[4], &sn, &cs);
            tc[tid] = cs; ts[tid] = sn;
            tl[tid] = labels[b * MM + tid];
        }
        int tot = nrow * KP1;
        const float* lg0 = logits + ((size_t)b * QQ + q0) * KP1;
        for (int i = tid; i < tot; i += 256) sprob[i] = lg0[i];
        __syncthreads();

        bool valid = tid < nrow;
        float p0 = 0, p1 = 0, p2 = 0, p3 = 0, pc = 0, psn = 0;
        if (valid) {
            float* r = sprob + tid * KP1;
            float l80 = r[KC];
            float mx = -FLT_MAX;
#pragma unroll 9
            for (int k = 0; k < KP1; k++) mx = fmaxf(mx, r[k]);
            float s = 0.f;
#pragma unroll 9
            for (int k = 0; k < KP1; k++) { float e = __expf(r[k] - mx); r[k] = e; s += e; }
            float inv = 1.f / s;
#pragma unroll 9
            for (int k = 0; k < KP1; k++) r[k] *= inv;
            float lse = mx + __logf(s);
            int q = q0 + tid;
            g_lse[b * QQ + q] = lse;
            g_b80[b * QQ + q] = lse - l80;
            const float* pb = pboxes + ((size_t)b * QQ + q) * 5;
            float sn, cs; sincosf(pb[4], &sn, &cs);
            p0 = pb[0]; p1 = pb[1]; p2 = pb[2]; p3 = pb[3]; pc = cs; psn = sn;
            pq0[tid] = p0; pq1[tid] = p1; pq2[tid] = p2; pq3[tid] = p3;
            pqc[tid] = cs; pqs[tid] = sn;
        }
        __syncthreads();

        if (valid) {
            const float* r = sprob + tid * KP1;
            float* outb = g_costT + (size_t)b * MM * QQ + (q0 + tid);
#pragma unroll 4
            for (int m = 0; m < MM; m++) {
                float prob = r[tl[m]];
                float l1 = fabsf(p0 - tn0[m]) + fabsf(p1 - tn1[m]) +
                           fabsf(p2 - tn2[m]) + fabsf(p3 - tn3[m]);
                float cosd = pc * tc[m] + psn * ts[m];
                outb[(size_t)m * QQ] = -2.f * prob + 5.f * l1 + 2.f * (1.f - cosd);
            }
        }

        // per-half-tile column top-4: thread = (m, half), half covers 64 rows
        {
            int m = tid & 127;
            int half = tid >> 7;
            int jb = half * 64;
            int je = min(jb + 64, nrow);
            int tile = t * 2 + half;
            float t0 = tn0[m], t1 = tn1[m], t2 = tn2[m], t3 = tn3[m];
            float tcc = tc[m], tss = ts[m];
            int lab = tl[m];
            unsigned long long e0 = DEAD64, e1 = DEAD64, e2 = DEAD64, e3 = DEAD64;
            for (int j = jb; j < je; j++) {
                float prob = sprob[j * KP1 + lab];
                float l1 = fabsf(pq0[j] - t0) + fabsf(pq1[j] - t1) +
                           fabsf(pq2[j] - t2) + fabsf(pq3[j] - t3);
                float cosd = pqc[j] * tcc + pqs[j] * tss;
                float v = -2.f * prob + 5.f * l1 + 2.f * (1.f - cosd);
                unsigned long long k = ((unsigned long long)ford(v) << 32) | (unsigned)(q0 + j);
                if (k < e3) {
                    if (k < e0)      { e3 = e2; e2 = e1; e1 = e0; e0 = k; }
                    else if (k < e1) { e3 = e2; e2 = e1; e1 = k; }
                    else if (k < e2) { e3 = e2; e2 = k; }
                    else             { e3 = k; }
                }
            }
            size_t idx = (((size_t)b * NT + tile) * MM + m) * 4;
            g_top[idx + 0] = e0; g_top[idx + 1] = e1;
            g_top[idx + 2] = e2; g_top[idx + 3] = e3;
        }
        __threadfence();
        __syncthreads();
        if (tid == 0) atomicAdd(&g_ready[b], 1u);

    } else {
        // ================= MATCH BLOCK: image b ===============================
        int b = bid - BB * 8;
        int lane = tid & 31, wid = tid >> 5;
        unsigned long long* S = (unsigned long long*)smraw;               // 4 KB
        unsigned long long (*ce)[4] = (unsigned long long(*)[4])(smraw + 4096); // 4 KB
        float* rmaskf = (float*)(smraw + 8192);                           // 4 KB
        int*   cused  = (int*)(smraw + 12288);                            // 512
        int*   colrem = (int*)(smraw + 12800);                            // 512
        unsigned long long* extras = (unsigned long long*)(smraw + 13312);// 512
        short* sq  = (short*)(smraw + 13824);
        short* smi = sq + MM;
        float* sb80 = (float*)(smraw + 14336);                            // QQ
        float* wsum = sb80 + QQ;
        float* buf  = wsum + 8;
        const float* C = g_costT + (size_t)b * MM * QQ;

        if (tid == 0) {
            while (*(volatile unsigned*)&g_ready[b] < 8u) __nanosleep(200);
            __threadfence();
        }
        __syncthreads();

        for (int q = tid; q < 1024; q += 256) rmaskf[q] = 0.f;
        if (tid < MM) { cused[tid] = 0; colrem[tid] = 4; }

        // merge 32 per-half-tile top-4 lists -> exact global top-4 per column
        if (tid < MM) {
            const unsigned long long* p = g_top + ((size_t)b * NT * MM + tid) * 4;
            unsigned long long e0 = DEAD64, e1 = DEAD64, e2 = DEAD64, e3 = DEAD64;
#pragma unroll
            for (int t = 0; t < NT; t++) {
#pragma unroll
                for (int r = 0; r < 4; r++) {
                    unsigned long long k = p[(size_t)t * MM * 4 + r];
                    if (k < e3) {
                        if (k < e0)      { e3 = e2; e2 = e1; e1 = e0; e0 = k; }
                        else if (k < e1) { e3 = e2; e2 = e1; e1 = k; }
                        else if (k < e2) { e3 = e2; e2 = k; }
                        else             { e3 = k; }
                    }
                }
            }
            ce[tid][0] = e0; ce[tid][1] = e1; ce[tid][2] = e2; ce[tid][3] = e3;
        }
        __syncthreads();

        // build 512 sort keys: (ford << 17) | (q << 7) | m
        for (int i = tid; i < 512; i += 256) {
            int m = i >> 2, r = i & 3;
            unsigned long long k = ce[m][r];
            S[i] = (k == DEAD64) ? DEAD64
                 : (((k >> 32) << 17) | (((unsigned long long)k & 0x3ffull) << 7)
                    | (unsigned long long)m);
        }
        // bitonic sort, 256 threads, 512 u64 keys
        for (int k = 2; k <= 512; k <<= 1) {
            for (int j = k >> 1; j > 0; j >>= 1) {
                __syncthreads();
                for (int i = tid; i < 512; i += 256) {
                    int l = i ^ j;
                    if (l > i) {
                        unsigned long long a = S[i], c = S[l];
                        bool up = ((i & k) == 0);
                        if ((a > c) == up) { S[i] = c; S[l] = a; }
                    }
                }
            }
        }
        __syncthreads();

        if (wid == 0) {
            // ============ sorted sweep (warp 0) ===============================
            int commits = 0, chunk = 0, ex_cnt = 0;
            unsigned long long ex_min = DEAD64;
            unsigned long long myk = S[lane];
            bool pending = (myk != DEAD64);
            int myq = (int)((myk >> 7) & 0x3ff);
            int mym = (int)(myk & 127);

            while (commits < MM) {
                __syncwarp();
                if (chunk < 16) {
                    // death processing
                    bool exh = false;
                    if (pending) {
                        if (cused[mym] != 0) pending = false;
                        else if (rmaskf[myq] != 0.f) {
                            pending = false;
                            int old = atomicSub(&colrem[mym], 1);
                            if (old == 1) exh = true;
                        }
                    }
                    unsigned ebal = __ballot_sync(FULL, exh);
                    while (ebal) {
                        int src = __ffs(ebal) - 1; ebal &= ebal - 1;
                        int mr = __shfl_sync(FULL, mym, src);
                        const float* col = C + (size_t)mr * QQ;
                        float nv = INFF; int nq = 0x3ff;
#pragma unroll 7
                        for (int j = 0; j < 28; j++) {
                            int q2 = lane + 32 * j;
                            float v = col[q2] + rmaskf[q2];
                            if (v < nv) { nv = v; nq = q2; }
                        }
                        { int q2 = lane + 896; if (q2 < QQ) { float v = col[q2] + rmaskf[q2]; if (v < nv) { nv = v; nq = q2; } } }
                        unsigned uu = ford(nv);
                        unsigned um = __reduce_min_sync(FULL, uu);
                        unsigned qq = (uu == um) ? (unsigned)nq : FULL;
                        unsigned qmn = __reduce_min_sync(FULL, qq);
                        unsigned long long nk = (((unsigned long long)um) << 17)
                                              | ((unsigned long long)qmn << 7)
                                              | (unsigned)mr;
                        if (lane == 0) extras[ex_cnt] = nk;
                        ex_cnt++;
                        if (nk < ex_min) ex_min = nk;
                    }
                    unsigned bal = __ballot_sync(FULL, pending);
                    if (!bal) {
                        chunk++;
                        if (chunk < 16) {
                            myk = S[chunk * 32 + lane];
                            pending = (myk != DEAD64);
                            myq = (int)((myk >> 7) & 0x3ff);
                            mym = (int)(myk & 127);
                        }
                        continue;
                    }
                    int L = __ffs(bal) - 1;
                    unsigned long long kL = __shfl_sync(FULL, myk, L);
                    if (!(ex_cnt > 0 && ex_min < kL)) {
                        if (lane == L) {
                            rmaskf[myq] = INFF; cused[mym] = 1;
                            sq[commits] = (short)myq; smi[commits] = (short)mym;
                            pending = false;
                        }
                        commits++;
                        continue;
                    }
                    // else fall through to extras path
                } else if (ex_cnt == 0) {
                    break;   // safety (should not happen)
                }

                // ---- extras candidate ex_min ----
                {
                    int mr = (int)(ex_min & 127);
                    int qr = (int)((ex_min >> 7) & 0x3ff);
                    if (rmaskf[qr] != 0.f) {
                        // stale: rescan column mr and replace slot
                        const float* col = C + (size_t)mr * QQ;
                        float nv = INFF; int nq = 0x3ff;
#pragma unroll 7
                        for (int j = 0; j < 28; j++) {
                            int q2 = lane + 32 * j;
                            float v = col[q2] + rmaskf[q2];
                            if (v < nv) { nv = v; nq = q2; }
                        }
                        { int q2 = lane + 896; if (q2 < QQ) { float v = col[q2] + rmaskf[q2]; if (v < nv) { nv = v; nq = q2; } } }
                        unsigned uu = ford(nv);
                        unsigned um = __reduce_min_sync(FULL, uu);
                        unsigned qq = (uu == um) ? (unsigned)nq : FULL;
                        unsigned qmn = __reduce_min_sync(FULL, qq);
                        unsigned long long nk = (((unsigned long long)um) << 17)
                                              | ((unsigned long long)qmn << 7)
                                              | (unsigned)mr;
                        unsigned long long em = DEAD64;
                        if (lane == 0) {
                            for (int i2 = 0; i2 < ex_cnt; i2++)
                                if (extras[i2] == ex_min) { extras[i2] = nk; break; }
                            for (int i2 = 0; i2 < ex_cnt; i2++)
                                if (extras[i2] < em) em = extras[i2];
                        }
                        ex_min = __shfl_sync(FULL, em, 0);
                        continue;
                    }
                    // commit extras entry
                    unsigned long long em = DEAD64;
                    if (lane == 0) {
                        rmaskf[qr] = INFF; cused[mr] = 1;
                        sq[commits] = (short)qr; smi[commits] = (short)mr;
                        for (int i2 = 0; i2 < ex_cnt; i2++)
                            if (extras[i2] == ex_min) { extras[i2] = extras[ex_cnt - 1]; break; }
                        for (int i2 = 0; i2 < ex_cnt - 1; i2++)
                            if (extras[i2] < em) em = extras[i2];
                    }
                    commits++; ex_cnt--;
                    ex_min = __shfl_sync(FULL, em, 0);
                }
            }
        } else {
            // warps 1-7: CE baseline (coalesced)
            float base = 0.f;
            for (int q = tid - 32; q < QQ; q += 224) {
                float v = g_b80[b * QQ + q];
                sb80[q] = v;
                base += v;
            }
            for (int o = 16; o; o >>= 1) base += __shfl_xor_sync(FULL, base, o);
            if (lane == 0) wsum[wid] = 0.1f * base;
        }
        __syncthreads();

        // ---- matched corrections ----
        float corr = 0.f, sb = 0.f, sa = 0.f;
        if (tid < MM) {
            int q = sq[tid], m = smi[tid];
            int lab = labels[b * MM + m];
            int row = b * QQ + q;
            corr = (g_lse[row] - logits[(size_t)row * KP1 + lab]) - 0.1f * sb80[q];
            float H = sizes[b * 2 + 0], W = sizes[b * 2 + 1];
            const float* pb = pboxes + ((size_t)b * QQ + q) * 5;
            const float* tb = tboxes + ((size_t)b * MM + m) * 5;
            sb = fabsf(pb[0] - tb[0] / W) + fabsf(pb[1] - tb[1] / H) +
                 fabsf(pb[2] - tb[2] / W) + fabsf(pb[3] - tb[3] / H);
            sa = 1.f - cosf(pb[4] - tb[4]);
        }

        buf[tid] = corr; __syncthreads();
        for (int s = 128; s > 0; s >>= 1) { if (tid < s) buf[tid] += buf[tid + s]; __syncthreads(); }
        float numt = buf[0]; __syncthreads();
        buf[tid] = sb; __syncthreads();
        for (int s = 128; s > 0; s >>= 1) { if (tid < s) buf[tid] += buf[tid + s]; __syncthreads(); }
        float sbt = buf[0]; __syncthreads();
        buf[tid] = sa; __syncthreads();
        for (int s = 128; s > 0; s >>= 1) { if (tid < s) buf[tid] += buf[tid + s]; __syncthreads(); }
        float sat = buf[0];

        if (tid == 0) {
#pragma unroll
            for (int w = 1; w < 8; w++) numt += wsum[w];
            atomicAdd(&g_acc[0], numt);
            atomicAdd(&g_acc[1], sbt);
            atomicAdd(&g_acc[2], sat);
            __threadfence();
            unsigned done = atomicAdd(&g_done, 1u);
            if (done == BB - 1) {
                const float den = 0.1f * (QQ - MM) + (float)MM;  // 205.2
                float lc = g_acc[0] / (den * BB);
                float lb = g_acc[1] * 5.f / (float)(MM * 4 * BB);
                float la = g_acc[2] * 2.f / (float)(MM * BB);
                out[0] = lc;
                out[1] = lb;
                out[2] = la;
                out[3] = lc + lb + la;
                g_acc[0] = 0.f; g_acc[1] = 0.f; g_acc[2] = 0.f;
                g_done = 0u;
            }
            g_ready[b] = 0u;
        }
    }
}

extern "C" void kernel_launch(void* const* d_in, const int* in_sizes, int n_in,
                              void* d_out, int out_size) {
    const float* logits = (const float*)d_in[0];
    const float* pboxes = (const float*)d_in[1];
    const float* tboxes = (const float*)d_in[2];
    const float* sizes  = (const float*)d_in[3];
    const int*   labels = (const int*)d_in[4];
    float* out = (float*)d_out;

    cudaFuncSetAttribute(k_fused, cudaFuncAttributeMaxDynamicSharedMemorySize,
                         SMEM_TOTAL);
    k_fused<<<BB * 8 + BB, 256, SMEM_TOTAL>>>(logits, pboxes, tboxes, sizes,
                                              labels, out);
}

// round 13
// speedup vs baseline: 1.4127x; 1.4127x over previous
#include <cuda_runtime.h>
#include <math.h>
#include <float.h>

#define BB 32
#define QQ 900
#define MM 128
#define KC 80
#define KP1 81
#define NT 16                      // q-tiles per image (8 blocks x 2 halves)
#define INFF __int_as_float(0x7f800000)
#define DEAD64 0xffffffffffffffffull
#define FULL 0xffffffffu

__device__ float g_costT[BB * MM * QQ];                 // [b][m][q] for rescans
__device__ unsigned long long g_top[BB * NT * MM * 4];
__device__ float g_lse[BB * QQ];
__device__ float g_b80[BB * QQ];
__device__ float g_acc[3];
__device__ unsigned g_done;
__device__ unsigned g_ready[BB];

__device__ __forceinline__ unsigned ford(float f) {
    unsigned u = __float_as_uint(f);
    return u ^ ((u >> 31) ? 0xffffffffu : 0x80000000u);
}

#define SMEM_TOTAL 49152

__global__ void __launch_bounds__(256) k_fused(
    const float* __restrict__ logits,
    const float* __restrict__ pboxes,
    const float* __restrict__ tboxes,
    const float* __restrict__ sizes,
    const int*   __restrict__ labels,
    float* __restrict__ out) {
    extern __shared__ char smraw[];
    int bid = blockIdx.x, tid = threadIdx.x;

    if (bid < BB * 8) {
        // ================= COST BLOCK: image b, one 128-row q-tile ============
        int b = bid >> 3, t = bid & 7;
        int q0 = t * 128;
        int nrow = min(128, QQ - q0);
        float* sprob = (float*)smraw;                 // 128*81 floats
        float* tn0 = sprob + 128 * KP1;
        float* tn1 = tn0 + MM; float* tn2 = tn1 + MM; float* tn3 = tn2 + MM;
        float* tc  = tn3 + MM; float* ts  = tc  + MM;
        int*   tl  = (int*)(ts + MM);
        float* pq0 = (float*)(tl + MM);
        float* pq1 = pq0 + 128; float* pq2 = pq1 + 128; float* pq3 = pq2 + 128;
        float* pqc = pq3 + 128; float* pqs = pqc + 128;

        float H = sizes[b * 2 + 0], W = sizes[b * 2 + 1];
        if (tid < MM) {
            const float* tb = tboxes + ((size_t)b * MM + tid) * 5;
            tn0[tid] = tb[0] / W; tn1[tid] = tb[1] / H;
            tn2[tid] = tb[2] / W; tn3[tid] = tb[3] / H;
            float sn, cs; sincosf(tb[4], &sn, &cs);
            tc[tid] = cs; ts[tid] = sn;
            tl[tid] = labels[b * MM + tid];
        }
        int tot = nrow * KP1;
        const float* lg0 = logits + ((size_t)b * QQ + q0) * KP1;
        for (int i = tid; i < tot; i += 256) sprob[i] = lg0[i];
        __syncthreads();

        bool valid = tid < nrow;
        float p0 = 0, p1 = 0, p2 = 0, p3 = 0, pc = 0, psn = 0;
        if (valid) {
            float* r = sprob + tid * KP1;             // stride 81: conflict-free
            float l80 = r[KC];
            float mx = -FLT_MAX;
#pragma unroll 9
            for (int k = 0; k < KP1; k++) mx = fmaxf(mx, r[k]);
            float s = 0.f;
#pragma unroll 9
            for (int k = 0; k < KP1; k++) { float e = __expf(r[k] - mx); r[k] = e; s += e; }
            float inv = 1.f / s;
#pragma unroll 9
            for (int k = 0; k < KP1; k++) r[k] *= inv;
            float lse = mx + __logf(s);
            int q = q0 + tid;
            g_lse[b * QQ + q] = lse;
            g_b80[b * QQ + q] = lse - l80;
            const float* pb = pboxes + ((size_t)b * QQ + q) * 5;
            float sn, cs; sincosf(pb[4], &sn, &cs);
            p0 = pb[0]; p1 = pb[1]; p2 = pb[2]; p3 = pb[3]; pc = cs; psn = sn;
            pq0[tid] = p0; pq1[tid] = p1; pq2[tid] = p2; pq3[tid] = p3;
            pqc[tid] = cs; pqs[tid] = sn;
        }
        __syncthreads();

        // ---- transposed cost tile (thread = q, coalesced along q) ----
        if (valid) {
            const float* r = sprob + tid * KP1;
            float* outb = g_costT + (size_t)b * MM * QQ + (q0 + tid);
#pragma unroll 4
            for (int m = 0; m < MM; m++) {
                float prob = r[tl[m]];
                float l1 = fabsf(p0 - tn0[m]) + fabsf(p1 - tn1[m]) +
                           fabsf(p2 - tn2[m]) + fabsf(p3 - tn3[m]);
                float cosd = pc * tc[m] + psn * ts[m];
                outb[(size_t)m * QQ] = -2.f * prob + 5.f * l1 + 2.f * (1.f - cosd);
            }
        }

        // ---- per-half-tile column top-4: thread = (m, half), 64 rows each ----
        {
            int m = tid & 127;
            int half = tid >> 7;
            int jb = half * 64;
            int je = min(jb + 64, nrow);
            int tile = t * 2 + half;
            float t0 = tn0[m], t1 = tn1[m], t2 = tn2[m], t3 = tn3[m];
            float tcc = tc[m], tss = ts[m];
            int lab = tl[m];
            unsigned long long e0 = DEAD64, e1 = DEAD64, e2 = DEAD64, e3 = DEAD64;
            for (int j = jb; j < je; j++) {
                float prob = sprob[j * KP1 + lab];
                float l1 = fabsf(pq0[j] - t0) + fabsf(pq1[j] - t1) +
                           fabsf(pq2[j] - t2) + fabsf(pq3[j] - t3);
                float cosd = pqc[j] * tcc + pqs[j] * tss;
                float v = -2.f * prob + 5.f * l1 + 2.f * (1.f - cosd);
                unsigned long long k = ((unsigned long long)ford(v) << 32) | (unsigned)(q0 + j);
                if (k < e3) {
                    if (k < e0)      { e3 = e2; e2 = e1; e1 = e0; e0 = k; }
                    else if (k < e1) { e3 = e2; e2 = e1; e1 = k; }
                    else if (k < e2) { e3 = e2; e2 = k; }
                    else             { e3 = k; }
                }
            }
            size_t idx = (((size_t)b * NT + tile) * MM + m) * 4;
            g_top[idx + 0] = e0; g_top[idx + 1] = e1;
            g_top[idx + 2] = e2; g_top[idx + 3] = e3;
        }
        __threadfence();
        __syncthreads();
        if (tid == 0) atomicAdd(&g_ready[b], 1u);

    } else {
        // ================= MATCH BLOCK: image b (R11 verbatim) ================
        int b = bid - BB * 8;
        int lane = tid & 31, wid = tid >> 5;
        unsigned long long (*ce)[4] = (unsigned long long(*)[4])smraw;    // 4 KB
        float* rmask = (float*)(smraw + 4096);                            // 4 KB
        short* sq  = (short*)(smraw + 8192);
        short* smi = sq + MM;
        float* sb80 = (float*)(smraw + 8704);                             // QQ floats
        float* wsum = sb80 + QQ;
        float* buf  = wsum + 8;
        const float* C = g_costT + (size_t)b * MM * QQ;

        // wait for this image's 8 producers
        if (tid == 0) {
            while (*(volatile unsigned*)&g_ready[b] < 8u) __nanosleep(200);
            __threadfence();
        }
        __syncthreads();

        for (int q = tid; q < 1024; q += 256) rmask[q] = 0.f;

        // ---- merge 16 per-tile top-4 lists into exact global top-4 ----
        if (tid < MM) {
            const unsigned long long* p = g_top + ((size_t)b * NT * MM + tid) * 4;
            unsigned long long e0 = DEAD64, e1 = DEAD64, e2 = DEAD64, e3 = DEAD64;
#pragma unroll
            for (int t = 0; t < NT; t++) {
#pragma unroll
                for (int r = 0; r < 4; r++) {
                    unsigned long long k = p[(size_t)t * MM * 4 + r];
                    if (k < e3) {
                        if (k < e0)      { e3 = e2; e2 = e1; e1 = e0; e0 = k; }
                        else if (k < e1) { e3 = e2; e2 = e1; e1 = k; }
                        else if (k < e2) { e3 = e2; e2 = k; }
                        else             { e3 = k; }
                    }
                }
            }
            ce[tid][0] = e0; ce[tid][1] = e1; ce[tid][2] = e2; ce[tid][3] = e3;
        }
        __syncthreads();

        if (wid == 0) {
            // ========== R8 matching loop (proven fastest) =====================
            unsigned long long e[4][4];
#pragma unroll
            for (int g = 0; g < 4; g++)
#pragma unroll
                for (int r = 0; r < 4; r++) e[g][r] = ce[lane + 32 * g][r];

            int it = 0;
            while (it < MM) {
                int nc = 0;
                unsigned myrq = FULL;
                while (nc < 32 && it + nc < MM) {
                    unsigned long long best = DEAD64;
#pragma unroll
                    for (int g = 0; g < 4; g++) {
                        unsigned long long h = e[g][0];
                        unsigned long long k2 = ((h >> 32) << 17)
                                              | (((unsigned)h & 0x3ffu) << 7)
                                              | (unsigned)(lane + 32 * g);
                        if (k2 < best) best = k2;
                    }
                    unsigned hi = (unsigned)(best >> 17);
                    unsigned himin = __reduce_min_sync(FULL, hi);
                    unsigned lo = (hi == himin) ? (unsigned)(best & 0x1ffffu) : FULL;
                    unsigned lomin = __reduce_min_sync(FULL, lo);
                    unsigned qs = lomin >> 7;
                    int ms = (int)(lomin & 127u);
                    if (__ballot_sync(FULL, lane < nc && myrq == qs))
                        break;                    // winner's row already in batch
                    if (lane == nc) myrq = qs;
                    if (lane == 0) { sq[it + nc] = (short)qs; smi[it + nc] = (short)ms; }
                    if (lane == (ms & 31)) {
                        int g = ms >> 5;
                        e[g][0] = DEAD64; e[g][1] = DEAD64; e[g][2] = DEAD64; e[g][3] = DEAD64;
                    }
                    nc++;
                }
                it += nc;
                if (lane < nc) rmask[myrq] = INFF;
                __syncwarp();
                if (it >= MM) break;

                // advance heads whose row is now masked
                bool r0 = false, r1 = false, r2 = false, r3 = false;
#pragma unroll
                for (int g = 0; g < 4; g++) {
                    if (e[g][0] == DEAD64) continue;
                    if (rmask[(unsigned)e[g][0] & 0x3ffu] != 0.f) {
                        do {
                            e[g][0] = e[g][1]; e[g][1] = e[g][2]; e[g][2] = e[g][3]; e[g][3] = DEAD64;
                        } while (e[g][0] != DEAD64 &&
                                 rmask[(unsigned)e[g][0] & 0x3ffu] != 0.f);
                        if (e[g][0] == DEAD64) {
                            if (g == 0) r0 = true; else if (g == 1) r1 = true;
                            else if (g == 2) r2 = true; else r3 = true;
                        }
                    }
                }
                // rare: list exhausted -> exact cooperative column rescan
                if (__ballot_sync(FULL, r0 | r1 | r2 | r3)) {
#pragma unroll
                    for (int g = 0; g < 4; g++) {
                        bool rg = (g == 0) ? r0 : (g == 1) ? r1 : (g == 2) ? r2 : r3;
                        unsigned bal = __ballot_sync(FULL, rg);
                        while (bal) {
                            int c = __ffs(bal) - 1; bal &= bal - 1;
                            int mr = c + 32 * g;
                            const float* col = C + (size_t)mr * QQ;
                            float nv = INFF; int nq = 0x3ff;
#pragma unroll 7
                            for (int j = 0; j < 28; j++) {
                                int q2 = lane + 32 * j;
                                float v = col[q2] + rmask[q2];
                                if (v < nv) { nv = v; nq = q2; }
                            }
                            { int q2 = lane + 896; if (q2 < QQ) { float v = col[q2] + rmask[q2]; if (v < nv) { nv = v; nq = q2; } } }
                            unsigned uu = ford(nv);
                            unsigned um = __reduce_min_sync(FULL, uu);
                            unsigned qq = (uu == um) ? (unsigned)nq : FULL;
                            unsigned qmn = __reduce_min_sync(FULL, qq);
                            if (lane == c)
                                e[g][0] = ((unsigned long long)um << 32) | qmn;
                            __syncwarp();
                        }
                    }
                }
                __syncwarp();
            }
        } else {
            // ---- warps 1-7: CE baseline (coalesced b80 load) ----
            float base = 0.f;
            for (int q = tid - 32; q < QQ; q += 224) {
                float v = g_b80[b * QQ + q];
                sb80[q] = v;
                base += v;
            }
            for (int o = 16; o; o >>= 1) base += __shfl_xor_sync(FULL, base, o);
            if (lane == 0) wsum[wid] = 0.1f * base;
        }
        __syncthreads();

        // ---- matched corrections ----
        float corr = 0.f, sb = 0.f, sa = 0.f;
        if (tid < MM) {
            int q = sq[tid], m = smi[tid];
            int lab = labels[b * MM + m];
            int row = b * QQ + q;
            corr = (g_lse[row] - logits[(size_t)row * KP1 + lab]) - 0.1f * sb80[q];
            float H = sizes[b * 2 + 0], W = sizes[b * 2 + 1];
            const float* pb = pboxes + ((size_t)b * QQ + q) * 5;
            const float* tb = tboxes + ((size_t)b * MM + m) * 5;
            sb = fabsf(pb[0] - tb[0] / W) + fabsf(pb[1] - tb[1] / H) +
                 fabsf(pb[2] - tb[2] / W) + fabsf(pb[3] - tb[3] / H);
            sa = 1.f - cosf(pb[4] - tb[4]);
        }

        buf[tid] = corr; __syncthreads();
        for (int s = 128; s > 0; s >>= 1) { if (tid < s) buf[tid] += buf[tid + s]; __syncthreads(); }
        float numt = buf[0]; __syncthreads();
        buf[tid] = sb; __syncthreads();
        for (int s = 128; s > 0; s >>= 1) { if (tid < s) buf[tid] += buf[tid + s]; __syncthreads(); }
        float sbt = buf[0]; __syncthreads();
        buf[tid] = sa; __syncthreads();
        for (int s = 128; s > 0; s >>= 1) { if (tid < s) buf[tid] += buf[tid + s]; __syncthreads(); }
        float sat = buf[0];

        if (tid == 0) {
#pragma unroll
            for (int w = 1; w < 8; w++) numt += wsum[w];
            atomicAdd(&g_acc[0], numt);
            atomicAdd(&g_acc[1], sbt);
            atomicAdd(&g_acc[2], sat);
            __threadfence();
            unsigned done = atomicAdd(&g_done, 1u);
            if (done == BB - 1) {
                const float den = 0.1f * (QQ - MM) + (float)MM;  // 205.2 per image
                float lc = g_acc[0] / (den * BB);
                float lb = g_acc[1] * 5.f / (float)(MM * 4 * BB);
                float la = g_acc[2] * 2.f / (float)(MM * BB);
                out[0] = lc;
                out[1] = lb;
                out[2] = la;
                out[3] = lc + lb + la;
                // reset state for the next (graph-replayed) launch
                g_acc[0] = 0.f; g_acc[1] = 0.f; g_acc[2] = 0.f;
                g_done = 0u;
            }
            g_ready[b] = 0u;                  // per-image reset for next launch
        }
    }
}

extern "C" void kernel_launch(void* const* d_in, const int* in_sizes, int n_in,
                              void* d_out, int out_size) {
    const float* logits = (const float*)d_in[0];   // [B,Q,81]
    const float* pboxes = (const float*)d_in[1];   // [B,Q,5]
    const float* tboxes = (const float*)d_in[2];   // [B,M,5]
    const float* sizes  = (const float*)d_in[3];   // [B,2]
    const int*   labels = (const int*)d_in[4];     // [B,M]
    float* out = (float*)d_out;

    cudaFuncSetAttribute(k_fused, cudaFuncAttributeMaxDynamicSharedMemorySize,
                         SMEM_TOTAL);
    k_fused<<<BB * 8 + BB, 256, SMEM_TOTAL>>>(logits, pboxes, tboxes, sizes,
                                              labels, out);
}